// round 8
// baseline (speedup 1.0000x reference)
#include <cuda_runtime.h>
#include <cuda_bf16.h>
#include <cstddef>
#include <cstdint>

typedef unsigned long long u64;
typedef unsigned int u32;
typedef __nv_bfloat16 bf16;

#define NCTA 148
#define NTHR 256
#define NSTAGE 3

// smem chunk layout (bytes): A 128x64 hi/lo (rows padded 144B), B 64x64 hi/lo
#define OFF_AL 18432
#define OFF_BH 36864
#define OFF_BL 46080
#define BUFSZ 55296

// ---------------- device scratch ----------------
__device__ float g_Xpre[(size_t)512 * 64 * 3072];  // [t][b][3072]
__device__ float g_H2[(size_t)512 * 64 * 1024];    // [t][b][1024]
__device__ float g_hbuf[2][3][65536];              // fp32 h (parity, layer) [b][n]
__device__ float g_z[3][65536];                    // z gate [b][n]
__device__ __align__(16) bf16 g_hbH[2][3][65536];
__device__ __align__(16) bf16 g_hbL[2][3][65536];
__device__ __align__(16) bf16 g_rhH[3][65536];
__device__ __align__(16) bf16 g_rhL[3][65536];
__device__ __align__(16) bf16 g_WhH[(size_t)3 * 3072 * 1024];  // l0=Wh0, l1/2=Whr
__device__ __align__(16) bf16 g_WhL[(size_t)3 * 3072 * 1024];
__device__ __align__(16) bf16 g_WxH[(size_t)2 * 3072 * 1024];  // Wxr
__device__ __align__(16) bf16 g_WxL[(size_t)2 * 3072 * 1024];
__device__ float g_part1[48][128 * 64];            // zr K-split partials [l*16+tt]
__device__ float g_part2[24][128 * 64];            // g  K-split partials [l*8+tt]
__device__ unsigned g_cnt;
__device__ volatile unsigned g_gen;

// ---------------- generic helpers ----------------
__device__ __forceinline__ u64 ffma2(u64 a, u64 b, u64 c) {
    u64 d;
    asm("fma.rn.f32x2 %0, %1, %2, %3;" : "=l"(d) : "l"(a), "l"(b), "l"(c));
    return d;
}
__device__ __forceinline__ float psum(u64 a) {
    float2 f = *reinterpret_cast<float2*>(&a);
    return f.x + f.y;
}
__device__ __forceinline__ float sigm(float x) { return 1.f / (1.f + __expf(-x)); }

__device__ __forceinline__ void gridbar() {
    __syncthreads();
    if (threadIdx.x == 0) {
        unsigned old = g_gen;
        __threadfence();
        if (atomicAdd(&g_cnt, 1u) == NCTA - 1) {
            g_cnt = 0;
            __threadfence();
            g_gen = old + 1;
        } else {
            while (g_gen == old) __nanosleep(32);
            __threadfence();
        }
    }
    __syncthreads();
}

// ---------------- mma / ldmatrix / cp.async primitives ----------------
__device__ __forceinline__ u32 smem_u32(const void* p) {
    u32 a;
    asm("{ .reg .u64 t; cvta.to.shared.u64 t, %1; cvt.u32.u64 %0, t; }" : "=r"(a) : "l"(p));
    return a;
}
__device__ __forceinline__ void mma16816(float* d, const u32* a, const u32* b) {
    asm volatile(
        "mma.sync.aligned.m16n8k16.row.col.f32.bf16.bf16.f32 "
        "{%0,%1,%2,%3}, {%4,%5,%6,%7}, {%8,%9}, {%0,%1,%2,%3};"
        : "+f"(d[0]), "+f"(d[1]), "+f"(d[2]), "+f"(d[3])
        : "r"(a[0]), "r"(a[1]), "r"(a[2]), "r"(a[3]), "r"(b[0]), "r"(b[1]));
}
__device__ __forceinline__ void ldm4(u32& r0, u32& r1, u32& r2, u32& r3, u32 addr) {
    asm volatile("ldmatrix.sync.aligned.m8n8.x4.shared.b16 {%0,%1,%2,%3}, [%4];"
                 : "=r"(r0), "=r"(r1), "=r"(r2), "=r"(r3) : "r"(addr));
}
__device__ __forceinline__ void cpa(u32 dst, const void* src) {
    asm volatile("cp.async.cg.shared.global [%0], [%1], 16;" :: "r"(dst), "l"(src) : "memory");
}
__device__ __forceinline__ void cp_commit() { asm volatile("cp.async.commit_group;" ::: "memory"); }
__device__ __forceinline__ void cp_wait0() { asm volatile("cp.async.wait_group 0;" ::: "memory"); }
__device__ __forceinline__ void cp_wait1() { asm volatile("cp.async.wait_group 1;" ::: "memory"); }

struct Src { const bf16 *AH, *AL, *BH, *BL; };

// issue one K=64 chunk into smem buffer (256 threads)
__device__ __forceinline__ void issue_chunk(u32 sbuf, const Src& s, int koff, int tid) {
#pragma unroll
    for (int it = 0; it < 4; it++) {
        int idx = tid + NTHR * it;
        int row = idx >> 3, c16 = idx & 7;
        u32 d = sbuf + row * 144 + c16 * 16;
        size_t so = (size_t)row * 1024 + koff + c16 * 8;
        cpa(d, s.AH + so);
        cpa(d + OFF_AL, s.AL + so);
    }
#pragma unroll
    for (int it = 0; it < 2; it++) {
        int idx = tid + NTHR * it;
        int row = idx >> 3, c16 = idx & 7;
        u32 d = sbuf + OFF_BH + row * 144 + c16 * 16;
        size_t so = (size_t)row * 1024 + koff + c16 * 8;
        cpa(d, s.BH + so);
        cpa(d + (OFF_BL - OFF_BH), s.BL + so);
    }
    cp_commit();
}

// compute one K=64 chunk (8 warps, each warp 16 weight-rows)
__device__ __forceinline__ void mma_chunk(u32 sbuf, float (&acc)[8][4], int wid, int lane) {
    const int arow = ((lane >> 3) & 1) * 8 + (lane & 7);
    const int akk = ((lane >> 4) & 1) * 8;
    const int brow = ((lane >> 4) & 1) * 8 + (lane & 7);
    const int bkk = ((lane >> 3) & 1) * 8;
#pragma unroll
    for (int ks = 0; ks < 4; ks++) {
        int kOff = ks * 16;
        u32 aH[4], aL[4];
        {
            int row = wid * 16 + arow;
            u32 ad = sbuf + row * 144 + (kOff + akk) * 2;
            ldm4(aH[0], aH[1], aH[2], aH[3], ad);
            ldm4(aL[0], aL[1], aL[2], aL[3], ad + OFF_AL);
        }
        u32 bH[8][2], bL[8][2];
#pragma unroll
        for (int p = 0; p < 4; p++) {
            int nrow = p * 16 + brow;
            u32 bd = sbuf + OFF_BH + nrow * 144 + (kOff + bkk) * 2;
            u32 r0, r1, r2, r3;
            ldm4(r0, r1, r2, r3, bd);
            bH[2 * p][0] = r0; bH[2 * p][1] = r1; bH[2 * p + 1][0] = r2; bH[2 * p + 1][1] = r3;
            ldm4(r0, r1, r2, r3, bd + (OFF_BL - OFF_BH));
            bL[2 * p][0] = r0; bL[2 * p][1] = r1; bL[2 * p + 1][0] = r2; bL[2 * p + 1][1] = r3;
        }
#pragma unroll
        for (int nt = 0; nt < 8; nt++) {
            mma16816(acc[nt], aH, bH[nt]);
            mma16816(acc[nt], aH, bL[nt]);
            mma16816(acc[nt], aL, bH[nt]);
        }
    }
}

// run nsrc sources x 8 chunks (K=512 each at kbase), 3-stage pipeline, 1 sync/chunk
__device__ __forceinline__ void run_sources(const Src* s, int nsrc, int kbase, u32 sm0,
                                            float (&acc)[8][4], int tid, int wid, int lane) {
    const int n = nsrc * 8;
    issue_chunk(sm0, s[0], kbase, tid);
    if (n > 1) issue_chunk(sm0 + BUFSZ, s[0 + (1 >> 3)], kbase + (1 & 7) * 64, tid);
    for (int i = 0; i < n; i++) {
        if (i + 1 < n) cp_wait1(); else cp_wait0();
        __syncthreads();
        int nx = i + 2;
        if (nx < n)
            issue_chunk(sm0 + (nx % NSTAGE) * BUFSZ, s[nx >> 3], kbase + (nx & 7) * 64, tid);
        mma_chunk(sm0 + (i % NSTAGE) * BUFSZ, acc, wid, lane);
    }
    __syncthreads();
}

__device__ __forceinline__ void zero_acc(float (&acc)[8][4]) {
#pragma unroll
    for (int j = 0; j < 8; j++)
#pragma unroll
        for (int e = 0; e < 4; e++) acc[j][e] = 0.f;
}

// ---------------- SIMT f32x2 GEMM (xpre / yout) ----------------
__device__ __forceinline__ void gemm_tile(const float* __restrict__ A, int lda,
                                          const float* __restrict__ W, int ldw,
                                          float* __restrict__ C, int cld,
                                          const float* __restrict__ bias, int nch,
                                          u64* __restrict__ Sm) {
    const int tid = threadIdx.x, tx = tid & 15, ty = tid >> 4;
    u64 acc[8][8];
#pragma unroll
    for (int i = 0; i < 8; i++)
#pragma unroll
        for (int j = 0; j < 8; j++) acc[i][j] = 0ull;
    u64 rA[8], rB[16];
#pragma unroll
    for (int it = 0; it < 8; it++) {
        int idx = tid + 128 * it, row = idx >> 4, k8 = idx & 15;
        rA[it] = *reinterpret_cast<const u64*>(A + (size_t)row * lda + (k8 << 1));
    }
#pragma unroll
    for (int it = 0; it < 16; it++) {
        int idx = tid + 128 * it, row = idx >> 4, k8 = idx & 15;
        rB[it] = *reinterpret_cast<const u64*>(W + (size_t)row * ldw + (k8 << 1));
    }
    for (int c = 0; c < nch; c++) {
        u64* Ab = Sm + (c & 1) * 3072;
        u64* Bb = Ab + 1024;
#pragma unroll
        for (int it = 0; it < 8; it++) {
            int idx = tid + 128 * it, row = idx >> 4, k8 = idx & 15;
            Ab[(row << 4) + (k8 ^ ((row >> 3) & 15))] = rA[it];
        }
#pragma unroll
        for (int it = 0; it < 16; it++) {
            int idx = tid + 128 * it, row = idx >> 4, k8 = idx & 15;
            Bb[(row << 4) + (k8 ^ ((row >> 3) & 15))] = rB[it];
        }
        __syncthreads();
        if (c + 1 < nch) {
            const float* A2 = A + (c + 1) * 32;
            const float* W2 = W + (c + 1) * 32;
#pragma unroll
            for (int it = 0; it < 8; it++) {
                int idx = tid + 128 * it, row = idx >> 4, k8 = idx & 15;
                rA[it] = *reinterpret_cast<const u64*>(A2 + (size_t)row * lda + (k8 << 1));
            }
#pragma unroll
            for (int it = 0; it < 16; it++) {
                int idx = tid + 128 * it, row = idx >> 4, k8 = idx & 15;
                rB[it] = *reinterpret_cast<const u64*>(W2 + (size_t)row * ldw + (k8 << 1));
            }
        }
#pragma unroll
        for (int k8 = 0; k8 < 16; k8++) {
            u64 a2[8], b2[8];
#pragma unroll
            for (int i = 0; i < 8; i++) a2[i] = Ab[((ty * 8 + i) << 4) + (k8 ^ ty)];
#pragma unroll
            for (int j = 0; j < 8; j++) b2[j] = Bb[((tx * 8 + j) << 4) + (k8 ^ tx)];
#pragma unroll
            for (int i = 0; i < 8; i++)
#pragma unroll
                for (int j = 0; j < 8; j++) acc[i][j] = ffma2(a2[i], b2[j], acc[i][j]);
        }
    }
#pragma unroll
    for (int i = 0; i < 8; i++)
#pragma unroll
        for (int j = 0; j < 8; j++) {
            float v = psum(acc[i][j]);
            if (bias) v += bias[tx * 8 + j];
            C[(size_t)(ty * 8 + i) * cld + tx * 8 + j] = v;
        }
    __syncthreads();
}

// ---------------- kernels ----------------
__global__ void k_pad() {}

__global__ void k_conv(const float* __restrict__ Wh0, const float* __restrict__ Whr,
                       const float* __restrict__ Wxr) {
    const size_t NWH = (size_t)3 * 3072 * 1024;
    const size_t NTOT = (size_t)5 * 3072 * 1024;
    for (size_t i = (size_t)blockIdx.x * blockDim.x + threadIdx.x; i < NTOT;
         i += (size_t)gridDim.x * blockDim.x) {
        float w;
        bf16 *H, *L;
        size_t o;
        if (i < NWH) {
            o = i;
            w = (i < (size_t)3072 * 1024) ? Wh0[i] : Whr[i - (size_t)3072 * 1024];
            H = g_WhH; L = g_WhL;
        } else {
            o = i - NWH;
            w = Wxr[o];
            H = g_WxH; L = g_WxL;
        }
        bf16 h = __float2bfloat16_rn(w);
        H[o] = h;
        L[o] = __float2bfloat16_rn(w - __bfloat162float(h));
    }
}

__global__ __launch_bounds__(128, 2) void k_xpre(const float* __restrict__ x,
                                                 const float* __restrict__ Wx0) {
    __shared__ __align__(16) u64 Sm[6144];
    int n0 = blockIdx.x * 128, s = blockIdx.y;
    gemm_tile(x + (size_t)s * 128, 512 * 128, Wx0 + (size_t)n0 * 128, 128,
              g_Xpre + (size_t)s * 64 * 3072 + n0, 3072, nullptr, 4, Sm);
}

// persistent wavefront GRU with mma.sync bf16-split GEMMs, K-split 2x
__global__ __launch_bounds__(NTHR) void k_gru(const float* __restrict__ bh0,
                                              const float* __restrict__ bhr) {
    extern __shared__ __align__(16) char dsm[];
    const u32 sm0 = smem_u32(dsm);
    const int tid = threadIdx.x, wid = tid >> 5, lane = tid & 31;
    const int cta = blockIdx.x;
    const int gtid = cta * NTHR + tid;

    for (int i = gtid; i < 2 * 3 * 65536; i += NCTA * NTHR) {
        (&g_hbuf[0][0][0])[i] = 0.f;
        (&g_hbH[0][0][0])[i] = __float2bfloat16_rn(0.f);
        (&g_hbL[0][0][0])[i] = __float2bfloat16_rn(0.f);
    }
    gridbar();

    // roles: cta<96 zr (l=cta/32, tt=(cta%32)/2, kh=cta&1); cta in [96,144) g
    int role, l = 0, tt = 0, kh = 0;
    if (cta < 96) { role = 0; l = cta >> 5; tt = (cta & 31) >> 1; kh = cta & 1; }
    else if (cta < 144) { int gi = cta - 96; role = 1; l = gi >> 4; tt = (gi & 15) >> 1; kh = gi & 1; }
    else role = 2;
    const int kbase = kh * 512;
    const int rlo = lane >> 2, cb = (lane & 3) * 2;

    float acc[8][4];

    for (int w = 0; w < 514; ++w) {
        const int rd = w & 1, wb = rd ^ 1;
        const int t = w - l;
        const bool act = (role < 2) && t >= 0 && t < 512;

        // ======== P1: zr GEMM halves + g x-path halves ========
        if (act && role == 0) {
            zero_acc(acc);
            Src s[2];
            int ns = 0;
            if (l > 0) {
                s[ns].AH = g_WxH + ((size_t)(l - 1) * 3072 + tt * 128) * 1024;
                s[ns].AL = g_WxL + ((size_t)(l - 1) * 3072 + tt * 128) * 1024;
                s[ns].BH = g_hbH[rd][l - 1];
                s[ns].BL = g_hbL[rd][l - 1];
                ns++;
            }
            s[ns].AH = g_WhH + ((size_t)l * 3072 + tt * 128) * 1024;
            s[ns].AL = g_WhL + ((size_t)l * 3072 + tt * 128) * 1024;
            s[ns].BH = g_hbH[rd][l];
            s[ns].BL = g_hbL[rd][l];
            ns++;
            run_sources(s, ns, kbase, sm0, acc, tid, wid, lane);
            if (kh == 1) {
                float* P = g_part1[l * 16 + tt];
#pragma unroll
                for (int half = 0; half < 2; half++) {
                    int mrow = wid * 16 + half * 8 + rlo;
#pragma unroll
                    for (int nt = 0; nt < 8; nt++)
#pragma unroll
                        for (int e = 0; e < 2; e++)
                            P[mrow * 64 + nt * 8 + cb + e] = acc[nt][half * 2 + e];
                }
            }
        } else if (act && role == 1) {
            zero_acc(acc);
            if (l > 0) {
                Src s;
                s.AH = g_WxH + ((size_t)(l - 1) * 3072 + 2048 + tt * 128) * 1024;
                s.AL = g_WxL + ((size_t)(l - 1) * 3072 + 2048 + tt * 128) * 1024;
                s.BH = g_hbH[rd][l - 1];
                s.BL = g_hbL[rd][l - 1];
                run_sources(&s, 1, kbase, sm0, acc, tid, wid, lane);
            }
        }
        gridbar();

        // ======== zrE: kh=0 zr CTAs combine + z/rh ========
        if (act && role == 0 && kh == 0) {
            const float* P = g_part1[l * 16 + tt];
            const float* bias = (l == 0) ? bh0 : bhr + (l - 1) * 3072;
#pragma unroll
            for (int half = 0; half < 2; half++) {
                int mrow = wid * 16 + half * 8 + rlo;
                int n = tt * 128 + mrow;
                float bv = bias[n];
                if (n < 1024) {
#pragma unroll
                    for (int nt = 0; nt < 8; nt++)
#pragma unroll
                        for (int e = 0; e < 2; e++) {
                            int b = nt * 8 + cb + e;
                            float v = acc[nt][half * 2 + e] + P[mrow * 64 + b] + bv;
                            if (l == 0) v += g_Xpre[((size_t)t * 64 + b) * 3072 + n];
                            g_z[l][b * 1024 + n] = sigm(v);
                        }
                } else {
                    int nn = n - 1024;
#pragma unroll
                    for (int nt = 0; nt < 8; nt++)
#pragma unroll
                        for (int e = 0; e < 2; e++) {
                            int b = nt * 8 + cb + e;
                            float v = acc[nt][half * 2 + e] + P[mrow * 64 + b] + bv;
                            if (l == 0) v += g_Xpre[((size_t)t * 64 + b) * 3072 + n];
                            float rv = sigm(v) * g_hbuf[rd][l][b * 1024 + nn];
                            bf16 hi = __float2bfloat16_rn(rv);
                            g_rhH[l][b * 1024 + nn] = hi;
                            g_rhL[l][b * 1024 + nn] =
                                __float2bfloat16_rn(rv - __bfloat162float(hi));
                        }
                }
            }
        }
        gridbar();

        // ======== P2: g rh-path halves ========
        if (act && role == 1) {
            Src s;
            s.AH = g_WhH + ((size_t)l * 3072 + 2048 + tt * 128) * 1024;
            s.AL = g_WhL + ((size_t)l * 3072 + 2048 + tt * 128) * 1024;
            s.BH = g_rhH[l];
            s.BL = g_rhL[l];
            run_sources(&s, 1, kbase, sm0, acc, tid, wid, lane);
            if (kh == 1) {
                float* P = g_part2[l * 8 + tt];
#pragma unroll
                for (int half = 0; half < 2; half++) {
                    int mrow = wid * 16 + half * 8 + rlo;
#pragma unroll
                    for (int nt = 0; nt < 8; nt++)
#pragma unroll
                        for (int e = 0; e < 2; e++)
                            P[mrow * 64 + nt * 8 + cb + e] = acc[nt][half * 2 + e];
                }
            }
        }
        gridbar();

        // ======== gE: kh=0 g CTAs combine + tanh + h update ========
        if (act && role == 1 && kh == 0) {
            const float* P = g_part2[l * 8 + tt];
            const float* bias = (l == 0) ? bh0 : bhr + (l - 1) * 3072;
#pragma unroll
            for (int half = 0; half < 2; half++) {
                int mrow = wid * 16 + half * 8 + rlo;
                int gc = tt * 128 + mrow;
                float bv = bias[2048 + gc];
#pragma unroll
                for (int nt = 0; nt < 8; nt++)
#pragma unroll
                    for (int e = 0; e < 2; e++) {
                        int b = nt * 8 + cb + e;
                        float v = acc[nt][half * 2 + e] + P[mrow * 64 + b] + bv;
                        if (l == 0) v += g_Xpre[((size_t)t * 64 + b) * 3072 + 2048 + gc];
                        float gg = tanhf(v);
                        float z = g_z[l][b * 1024 + gc];
                        float hp = g_hbuf[rd][l][b * 1024 + gc];
                        float hn = z * hp + (1.f - z) * gg;
                        g_hbuf[wb][l][b * 1024 + gc] = hn;
                        bf16 hi = __float2bfloat16_rn(hn);
                        g_hbH[wb][l][b * 1024 + gc] = hi;
                        g_hbL[wb][l][b * 1024 + gc] =
                            __float2bfloat16_rn(hn - __bfloat162float(hi));
                        if (l == 2) g_H2[((size_t)t * 64 + b) * 1024 + gc] = hn;
                    }
            }
        }
        gridbar();
    }
}

__global__ __launch_bounds__(128, 2) void k_yout(const float* __restrict__ Wout,
                                                 const float* __restrict__ bout,
                                                 float* __restrict__ out) {
    __shared__ __align__(16) u64 Sm[6144];
    int s = blockIdx.x;
    gemm_tile(g_H2 + (size_t)s * 64 * 1024, 1024, Wout, 1024,
              out + (size_t)s * 128, 512 * 128, bout, 32, Sm);
}

__global__ void k_hout(float* __restrict__ out) {
    int i = blockIdx.x * 256 + threadIdx.x;
    if (i >= 3 * 64 * 1024) return;
    int l = i / (64 * 1024);
    int r = i % (64 * 1024);
    int b = r / 1024, n = r % 1024;
    out[(size_t)64 * 512 * 128 + ((size_t)b * 3 + l) * 1024 + n] = g_hbuf[l & 1][l][r];
}

extern "C" void kernel_launch(void* const* d_in, const int* in_sizes, int n_in,
                              void* d_out, int out_size) {
    const float* x = (const float*)d_in[0];
    const float* Wx0 = (const float*)d_in[1];
    const float* Wh0 = (const float*)d_in[2];
    const float* bh0 = (const float*)d_in[3];
    const float* Wxr = (const float*)d_in[4];
    const float* Whr = (const float*)d_in[5];
    const float* bhr = (const float*)d_in[6];
    const float* Wout = (const float*)d_in[7];
    const float* bout = (const float*)d_in[8];
    float* out = (float*)d_out;

    cudaFuncSetAttribute(k_gru, cudaFuncAttributeMaxDynamicSharedMemorySize, NSTAGE * BUFSZ);

    k_pad<<<1, 32>>>();
    k_pad<<<1, 32>>>();
    k_pad<<<1, 32>>>();
    k_conv<<<2048, 256>>>(Wh0, Whr, Wxr);
    k_xpre<<<dim3(24, 512), 128>>>(x, Wx0);
    k_gru<<<NCTA, NTHR, NSTAGE * BUFSZ>>>(bh0, bhr);  // 6th launch -> ncu -s 5
    k_yout<<<512, 128>>>(Wout, bout, out);
    k_hout<<<(3 * 64 * 1024 + 255) / 256, 256>>>(out);
}

// round 9
// speedup vs baseline: 1.9620x; 1.9620x over previous
#include <cuda_runtime.h>
#include <cuda_bf16.h>
#include <cstddef>
#include <cstdint>

typedef unsigned long long u64;
typedef unsigned int u32;
typedef __nv_bfloat16 bf16;

#define NCTA 148
#define NTHR 256
#define NSTAGE 3

// smem chunk layout (bytes): A 128x64 hi/lo (rows padded 144B), B 32x64 hi/lo
#define OFF_AL 18432
#define OFF_BH 36864
#define OFF_BL 41472
#define BUFSZ 46080

// ---------------- device scratch ----------------
__device__ float g_Xpre[(size_t)512 * 64 * 3072];  // [t][b][3072]
__device__ float g_H2[(size_t)512 * 64 * 1024];    // [t][b][1024]
__device__ float g_hbuf[2][3][65536];              // fp32 h (parity, layer) [b][n]
__device__ float g_z[3][65536];                    // z gate [b][n]
__device__ __align__(16) bf16 g_hbH[2][3][65536];
__device__ __align__(16) bf16 g_hbL[2][3][65536];
__device__ __align__(16) bf16 g_rhH[3][65536];
__device__ __align__(16) bf16 g_rhL[3][65536];
__device__ __align__(16) bf16 g_WhH[(size_t)3 * 3072 * 1024];  // l0=Wh0, l1/2=Whr
__device__ __align__(16) bf16 g_WhL[(size_t)3 * 3072 * 1024];
__device__ __align__(16) bf16 g_WxH[(size_t)2 * 3072 * 1024];  // Wxr
__device__ __align__(16) bf16 g_WxL[(size_t)2 * 3072 * 1024];
__device__ unsigned g_cnt;
__device__ volatile unsigned g_gen;

// ---------------- generic helpers ----------------
__device__ __forceinline__ u64 ffma2(u64 a, u64 b, u64 c) {
    u64 d;
    asm("fma.rn.f32x2 %0, %1, %2, %3;" : "=l"(d) : "l"(a), "l"(b), "l"(c));
    return d;
}
__device__ __forceinline__ float psum(u64 a) {
    float2 f = *reinterpret_cast<float2*>(&a);
    return f.x + f.y;
}
__device__ __forceinline__ float sigm(float x) { return 1.f / (1.f + __expf(-x)); }

__device__ __forceinline__ void gridbar() {
    __syncthreads();
    if (threadIdx.x == 0) {
        unsigned old = g_gen;
        __threadfence();
        if (atomicAdd(&g_cnt, 1u) == NCTA - 1) {
            g_cnt = 0;
            __threadfence();
            g_gen = old + 1;
        } else {
            while (g_gen == old) __nanosleep(32);
            __threadfence();
        }
    }
    __syncthreads();
}

// ---------------- mma / ldmatrix / cp.async primitives ----------------
__device__ __forceinline__ u32 smem_u32(const void* p) {
    u32 a;
    asm("{ .reg .u64 t; cvta.to.shared.u64 t, %1; cvt.u32.u64 %0, t; }" : "=r"(a) : "l"(p));
    return a;
}
__device__ __forceinline__ void mma16816(float* d, const u32* a, const u32* b) {
    asm volatile(
        "mma.sync.aligned.m16n8k16.row.col.f32.bf16.bf16.f32 "
        "{%0,%1,%2,%3}, {%4,%5,%6,%7}, {%8,%9}, {%0,%1,%2,%3};"
        : "+f"(d[0]), "+f"(d[1]), "+f"(d[2]), "+f"(d[3])
        : "r"(a[0]), "r"(a[1]), "r"(a[2]), "r"(a[3]), "r"(b[0]), "r"(b[1]));
}
__device__ __forceinline__ void ldm4(u32& r0, u32& r1, u32& r2, u32& r3, u32 addr) {
    asm volatile("ldmatrix.sync.aligned.m8n8.x4.shared.b16 {%0,%1,%2,%3}, [%4];"
                 : "=r"(r0), "=r"(r1), "=r"(r2), "=r"(r3) : "r"(addr));
}
__device__ __forceinline__ void cpa(u32 dst, const void* src) {
    asm volatile("cp.async.cg.shared.global [%0], [%1], 16;" :: "r"(dst), "l"(src) : "memory");
}
__device__ __forceinline__ void cp_commit() { asm volatile("cp.async.commit_group;" ::: "memory"); }
__device__ __forceinline__ void cp_wait0() { asm volatile("cp.async.wait_group 0;" ::: "memory"); }
__device__ __forceinline__ void cp_wait1() { asm volatile("cp.async.wait_group 1;" ::: "memory"); }

struct Src { const bf16 *AH, *AL, *BH, *BL; };

// issue one K=64 chunk (A 128x64 hi/lo, B 32x64 hi/lo) into smem buffer
__device__ __forceinline__ void issue_chunk(u32 sbuf, const Src& s, int koff, int tid) {
#pragma unroll
    for (int it = 0; it < 4; it++) {
        int idx = tid + NTHR * it;
        int row = idx >> 3, c16 = idx & 7;
        u32 d = sbuf + row * 144 + c16 * 16;
        size_t so = (size_t)row * 1024 + koff + c16 * 8;
        cpa(d, s.AH + so);
        cpa(d + OFF_AL, s.AL + so);
    }
    {
        int row = tid >> 3, c16 = tid & 7;
        u32 d = sbuf + OFF_BH + row * 144 + c16 * 16;
        size_t so = (size_t)row * 1024 + koff + c16 * 8;
        cpa(d, s.BH + so);
        cpa(d + (OFF_BL - OFF_BH), s.BL + so);
    }
    cp_commit();
}

// compute one K=64 chunk (8 warps x 16 weight-rows, N=32)
__device__ __forceinline__ void mma_chunk(u32 sbuf, float (&acc)[4][4], int wid, int lane) {
    const int arow = ((lane >> 3) & 1) * 8 + (lane & 7);
    const int akk = ((lane >> 4) & 1) * 8;
    const int brow = ((lane >> 4) & 1) * 8 + (lane & 7);
    const int bkk = ((lane >> 3) & 1) * 8;
#pragma unroll
    for (int ks = 0; ks < 4; ks++) {
        int kOff = ks * 16;
        u32 aH[4], aL[4];
        {
            int row = wid * 16 + arow;
            u32 ad = sbuf + row * 144 + (kOff + akk) * 2;
            ldm4(aH[0], aH[1], aH[2], aH[3], ad);
            ldm4(aL[0], aL[1], aL[2], aL[3], ad + OFF_AL);
        }
        u32 bH[4][2], bL[4][2];
#pragma unroll
        for (int p = 0; p < 2; p++) {
            int nrow = p * 16 + brow;
            u32 bd = sbuf + OFF_BH + nrow * 144 + (kOff + bkk) * 2;
            u32 r0, r1, r2, r3;
            ldm4(r0, r1, r2, r3, bd);
            bH[2 * p][0] = r0; bH[2 * p][1] = r1; bH[2 * p + 1][0] = r2; bH[2 * p + 1][1] = r3;
            ldm4(r0, r1, r2, r3, bd + (OFF_BL - OFF_BH));
            bL[2 * p][0] = r0; bL[2 * p][1] = r1; bL[2 * p + 1][0] = r2; bL[2 * p + 1][1] = r3;
        }
#pragma unroll
        for (int nt = 0; nt < 4; nt++) {
            mma16816(acc[nt], aH, bH[nt]);
            mma16816(acc[nt], aH, bL[nt]);
            mma16816(acc[nt], aL, bH[nt]);
        }
    }
}

// run nsrc sources x 16 chunks (full K=1024), 3-stage pipeline, 1 sync/chunk
__device__ __forceinline__ void run_sources(const Src* s, int nsrc, u32 sm0,
                                            float (&acc)[4][4], int tid, int wid, int lane) {
    const int n = nsrc * 16;
    issue_chunk(sm0, s[0], 0, tid);
    if (n > 1) issue_chunk(sm0 + BUFSZ, s[1 >> 4], (1 & 15) * 64, tid);
    for (int i = 0; i < n; i++) {
        if (i + 1 < n) cp_wait1(); else cp_wait0();
        __syncthreads();
        int nx = i + 2;
        if (nx < n)
            issue_chunk(sm0 + (nx % NSTAGE) * BUFSZ, s[nx >> 4], (nx & 15) * 64, tid);
        mma_chunk(sm0 + (i % NSTAGE) * BUFSZ, acc, wid, lane);
    }
    __syncthreads();
}

__device__ __forceinline__ void zero_acc(float (&acc)[4][4]) {
#pragma unroll
    for (int j = 0; j < 4; j++)
#pragma unroll
        for (int e = 0; e < 4; e++) acc[j][e] = 0.f;
}

// ---------------- SIMT f32x2 GEMM (xpre / yout) ----------------
__device__ __forceinline__ void gemm_tile(const float* __restrict__ A, int lda,
                                          const float* __restrict__ W, int ldw,
                                          float* __restrict__ C, int cld,
                                          const float* __restrict__ bias, int nch,
                                          u64* __restrict__ Sm) {
    const int tid = threadIdx.x, tx = tid & 15, ty = tid >> 4;
    u64 acc[8][8];
#pragma unroll
    for (int i = 0; i < 8; i++)
#pragma unroll
        for (int j = 0; j < 8; j++) acc[i][j] = 0ull;
    u64 rA[8], rB[16];
#pragma unroll
    for (int it = 0; it < 8; it++) {
        int idx = tid + 128 * it, row = idx >> 4, k8 = idx & 15;
        rA[it] = *reinterpret_cast<const u64*>(A + (size_t)row * lda + (k8 << 1));
    }
#pragma unroll
    for (int it = 0; it < 16; it++) {
        int idx = tid + 128 * it, row = idx >> 4, k8 = idx & 15;
        rB[it] = *reinterpret_cast<const u64*>(W + (size_t)row * ldw + (k8 << 1));
    }
    for (int c = 0; c < nch; c++) {
        u64* Ab = Sm + (c & 1) * 3072;
        u64* Bb = Ab + 1024;
#pragma unroll
        for (int it = 0; it < 8; it++) {
            int idx = tid + 128 * it, row = idx >> 4, k8 = idx & 15;
            Ab[(row << 4) + (k8 ^ ((row >> 3) & 15))] = rA[it];
        }
#pragma unroll
        for (int it = 0; it < 16; it++) {
            int idx = tid + 128 * it, row = idx >> 4, k8 = idx & 15;
            Bb[(row << 4) + (k8 ^ ((row >> 3) & 15))] = rB[it];
        }
        __syncthreads();
        if (c + 1 < nch) {
            const float* A2 = A + (c + 1) * 32;
            const float* W2 = W + (c + 1) * 32;
#pragma unroll
            for (int it = 0; it < 8; it++) {
                int idx = tid + 128 * it, row = idx >> 4, k8 = idx & 15;
                rA[it] = *reinterpret_cast<const u64*>(A2 + (size_t)row * lda + (k8 << 1));
            }
#pragma unroll
            for (int it = 0; it < 16; it++) {
                int idx = tid + 128 * it, row = idx >> 4, k8 = idx & 15;
                rB[it] = *reinterpret_cast<const u64*>(W2 + (size_t)row * ldw + (k8 << 1));
            }
        }
#pragma unroll
        for (int k8 = 0; k8 < 16; k8++) {
            u64 a2[8], b2[8];
#pragma unroll
            for (int i = 0; i < 8; i++) a2[i] = Ab[((ty * 8 + i) << 4) + (k8 ^ ty)];
#pragma unroll
            for (int j = 0; j < 8; j++) b2[j] = Bb[((tx * 8 + j) << 4) + (k8 ^ tx)];
#pragma unroll
            for (int i = 0; i < 8; i++)
#pragma unroll
                for (int j = 0; j < 8; j++) acc[i][j] = ffma2(a2[i], b2[j], acc[i][j]);
        }
    }
#pragma unroll
    for (int i = 0; i < 8; i++)
#pragma unroll
        for (int j = 0; j < 8; j++) {
            float v = psum(acc[i][j]);
            if (bias) v += bias[tx * 8 + j];
            C[(size_t)(ty * 8 + i) * cld + tx * 8 + j] = v;
        }
    __syncthreads();
}

// ---------------- kernels ----------------
__global__ void k_pad() {}

__global__ void k_conv(const float* __restrict__ Wh0, const float* __restrict__ Whr,
                       const float* __restrict__ Wxr) {
    const size_t NWH = (size_t)3 * 3072 * 1024;
    const size_t NTOT = (size_t)5 * 3072 * 1024;
    for (size_t i = (size_t)blockIdx.x * blockDim.x + threadIdx.x; i < NTOT;
         i += (size_t)gridDim.x * blockDim.x) {
        float w;
        bf16 *H, *L;
        size_t o;
        if (i < NWH) {
            o = i;
            w = (i < (size_t)3072 * 1024) ? Wh0[i] : Whr[i - (size_t)3072 * 1024];
            H = g_WhH; L = g_WhL;
        } else {
            o = i - NWH;
            w = Wxr[o];
            H = g_WxH; L = g_WxL;
        }
        bf16 h = __float2bfloat16_rn(w);
        H[o] = h;
        L[o] = __float2bfloat16_rn(w - __bfloat162float(h));
    }
}

__global__ __launch_bounds__(128, 2) void k_xpre(const float* __restrict__ x,
                                                 const float* __restrict__ Wx0) {
    __shared__ __align__(16) u64 Sm[6144];
    int n0 = blockIdx.x * 128, s = blockIdx.y;
    gemm_tile(x + (size_t)s * 128, 512 * 128, Wx0 + (size_t)n0 * 128, 128,
              g_Xpre + (size_t)s * 64 * 3072 + n0, 3072, nullptr, 4, Sm);
}

// persistent wavefront GRU: mma.sync bf16-split, batch-split x2, 2 barriers/wave
__global__ __launch_bounds__(NTHR) void k_gru(const float* __restrict__ bh0,
                                              const float* __restrict__ bhr) {
    extern __shared__ __align__(16) char dsm[];
    const u32 sm0 = smem_u32(dsm);
    const int tid = threadIdx.x, wid = tid >> 5, lane = tid & 31;
    const int cta = blockIdx.x;
    const int gtid = cta * NTHR + tid;

    for (int i = gtid; i < 2 * 3 * 65536; i += NCTA * NTHR) {
        (&g_hbuf[0][0][0])[i] = 0.f;
        (&g_hbH[0][0][0])[i] = __float2bfloat16_rn(0.f);
        (&g_hbL[0][0][0])[i] = __float2bfloat16_rn(0.f);
    }
    gridbar();

    // roles: cta<96 zr (l=cta/32, tt=(cta%32)/2, nh=cta&1); cta in [96,144) g
    int role, l = 0, tt = 0, nh = 0;
    if (cta < 96) { role = 0; l = cta >> 5; tt = (cta & 31) >> 1; nh = cta & 1; }
    else if (cta < 144) { int gi = cta - 96; role = 1; l = gi >> 4; tt = (gi & 15) >> 1; nh = gi & 1; }
    else role = 2;
    const int boff = nh * 32;           // batch-column offset of this CTA
    const size_t bptr = (size_t)boff * 1024;
    const int rlo = lane >> 2, cb = (lane & 3) * 2;

    float acc[4][4];

    for (int w = 0; w < 514; ++w) {
        const int rd = w & 1, wb = rd ^ 1;
        const int t = w - l;
        const bool act = (role < 2) && t >= 0 && t < 512;

        // ======== P1: zr full GEMMs + g x-path ========
        if (act && role == 0) {
            zero_acc(acc);
            Src s[2];
            int ns = 0;
            if (l > 0) {
                s[ns].AH = g_WxH + ((size_t)(l - 1) * 3072 + tt * 128) * 1024;
                s[ns].AL = g_WxL + ((size_t)(l - 1) * 3072 + tt * 128) * 1024;
                s[ns].BH = g_hbH[rd][l - 1] + bptr;
                s[ns].BL = g_hbL[rd][l - 1] + bptr;
                ns++;
            }
            s[ns].AH = g_WhH + ((size_t)l * 3072 + tt * 128) * 1024;
            s[ns].AL = g_WhL + ((size_t)l * 3072 + tt * 128) * 1024;
            s[ns].BH = g_hbH[rd][l] + bptr;
            s[ns].BL = g_hbL[rd][l] + bptr;
            ns++;
            run_sources(s, ns, sm0, acc, tid, wid, lane);
            // epilogue: z (n<1024) or rh (n>=1024)
            const float* bias = (l == 0) ? bh0 : bhr + (l - 1) * 3072;
#pragma unroll
            for (int half = 0; half < 2; half++) {
                int mrow = wid * 16 + half * 8 + rlo;
                int n = tt * 128 + mrow;
                float bv = bias[n];
                if (n < 1024) {
#pragma unroll
                    for (int nt = 0; nt < 4; nt++)
#pragma unroll
                        for (int e = 0; e < 2; e++) {
                            int b = boff + nt * 8 + cb + e;
                            float v = acc[nt][half * 2 + e] + bv;
                            if (l == 0) v += g_Xpre[((size_t)t * 64 + b) * 3072 + n];
                            g_z[l][b * 1024 + n] = sigm(v);
                        }
                } else {
                    int nn = n - 1024;
#pragma unroll
                    for (int nt = 0; nt < 4; nt++)
#pragma unroll
                        for (int e = 0; e < 2; e++) {
                            int b = boff + nt * 8 + cb + e;
                            float v = acc[nt][half * 2 + e] + bv;
                            if (l == 0) v += g_Xpre[((size_t)t * 64 + b) * 3072 + n];
                            float rv = sigm(v) * g_hbuf[rd][l][b * 1024 + nn];
                            bf16 hi = __float2bfloat16_rn(rv);
                            g_rhH[l][b * 1024 + nn] = hi;
                            g_rhL[l][b * 1024 + nn] =
                                __float2bfloat16_rn(rv - __bfloat162float(hi));
                        }
                }
            }
        } else if (act && role == 1) {
            zero_acc(acc);
            if (l > 0) {
                Src s;
                s.AH = g_WxH + ((size_t)(l - 1) * 3072 + 2048 + tt * 128) * 1024;
                s.AL = g_WxL + ((size_t)(l - 1) * 3072 + 2048 + tt * 128) * 1024;
                s.BH = g_hbH[rd][l - 1] + bptr;
                s.BL = g_hbL[rd][l - 1] + bptr;
                run_sources(&s, 1, sm0, acc, tid, wid, lane);
            }
        }
        gridbar();

        // ======== P2: g rh-path + epilogue ========
        if (act && role == 1) {
            Src s;
            s.AH = g_WhH + ((size_t)l * 3072 + 2048 + tt * 128) * 1024;
            s.AL = g_WhL + ((size_t)l * 3072 + 2048 + tt * 128) * 1024;
            s.BH = g_rhH[l] + bptr;
            s.BL = g_rhL[l] + bptr;
            run_sources(&s, 1, sm0, acc, tid, wid, lane);
            const float* bias = (l == 0) ? bh0 : bhr + (l - 1) * 3072;
#pragma unroll
            for (int half = 0; half < 2; half++) {
                int mrow = wid * 16 + half * 8 + rlo;
                int gc = tt * 128 + mrow;
                float bv = bias[2048 + gc];
#pragma unroll
                for (int nt = 0; nt < 4; nt++)
#pragma unroll
                    for (int e = 0; e < 2; e++) {
                        int b = boff + nt * 8 + cb + e;
                        float v = acc[nt][half * 2 + e] + bv;
                        if (l == 0) v += g_Xpre[((size_t)t * 64 + b) * 3072 + 2048 + gc];
                        float gg = tanhf(v);
                        float z = g_z[l][b * 1024 + gc];
                        float hp = g_hbuf[rd][l][b * 1024 + gc];
                        float hn = z * hp + (1.f - z) * gg;
                        g_hbuf[wb][l][b * 1024 + gc] = hn;
                        bf16 hi = __float2bfloat16_rn(hn);
                        g_hbH[wb][l][b * 1024 + gc] = hi;
                        g_hbL[wb][l][b * 1024 + gc] =
                            __float2bfloat16_rn(hn - __bfloat162float(hi));
                        if (l == 2) g_H2[((size_t)t * 64 + b) * 1024 + gc] = hn;
                    }
            }
        }
        gridbar();
    }
}

__global__ __launch_bounds__(128, 2) void k_yout(const float* __restrict__ Wout,
                                                 const float* __restrict__ bout,
                                                 float* __restrict__ out) {
    __shared__ __align__(16) u64 Sm[6144];
    int s = blockIdx.x;
    gemm_tile(g_H2 + (size_t)s * 64 * 1024, 1024, Wout, 1024,
              out + (size_t)s * 128, 512 * 128, bout, 32, Sm);
}

__global__ void k_hout(float* __restrict__ out) {
    int i = blockIdx.x * 256 + threadIdx.x;
    if (i >= 3 * 64 * 1024) return;
    int l = i / (64 * 1024);
    int r = i % (64 * 1024);
    int b = r / 1024, n = r % 1024;
    out[(size_t)64 * 512 * 128 + ((size_t)b * 3 + l) * 1024 + n] = g_hbuf[l & 1][l][r];
}

extern "C" void kernel_launch(void* const* d_in, const int* in_sizes, int n_in,
                              void* d_out, int out_size) {
    const float* x = (const float*)d_in[0];
    const float* Wx0 = (const float*)d_in[1];
    const float* Wh0 = (const float*)d_in[2];
    const float* bh0 = (const float*)d_in[3];
    const float* Wxr = (const float*)d_in[4];
    const float* Whr = (const float*)d_in[5];
    const float* bhr = (const float*)d_in[6];
    const float* Wout = (const float*)d_in[7];
    const float* bout = (const float*)d_in[8];
    float* out = (float*)d_out;

    cudaFuncSetAttribute(k_gru, cudaFuncAttributeMaxDynamicSharedMemorySize, NSTAGE * BUFSZ);

    k_pad<<<1, 32>>>();
    k_conv<<<2048, 256>>>(Wh0, Whr, Wxr);
    k_xpre<<<dim3(24, 512), 128>>>(x, Wx0);
    k_gru<<<NCTA, NTHR, NSTAGE * BUFSZ>>>(bh0, bhr);  // my 4th launch -> ncu -s 5
    k_yout<<<512, 128>>>(Wout, bout, out);
    k_hout<<<(3 * 64 * 1024 + 255) / 256, 256>>>(out);
}

// round 10
// speedup vs baseline: 2.1465x; 1.0940x over previous
#include <cuda_runtime.h>
#include <cuda_bf16.h>
#include <cstddef>
#include <cstdint>

typedef unsigned long long u64;
typedef unsigned int u32;
typedef __nv_bfloat16 bf16;

#define NCTA 148
#define NTHR 512
#define NSTAGE 5

// smem chunk layout (bytes): A 128x64 hi/lo (rows padded 144B), B 32x64 hi/lo
#define OFF_AL 18432
#define OFF_BH 36864
#define OFF_BL 41472
#define BUFSZ 46080

// ---------------- device scratch ----------------
__device__ float g_Xpre[(size_t)512 * 64 * 3072];  // [t][b][3072]
__device__ float g_H2[(size_t)512 * 64 * 1024];    // [t][b][1024]
__device__ float g_hbuf[2][3][65536];              // fp32 h (parity, layer) [b][n]
__device__ float g_z[3][65536];                    // z gate [b][n]
__device__ __align__(16) bf16 g_hbH[2][3][65536];
__device__ __align__(16) bf16 g_hbL[2][3][65536];
__device__ __align__(16) bf16 g_rhH[3][65536];
__device__ __align__(16) bf16 g_rhL[3][65536];
__device__ __align__(16) bf16 g_WhH[(size_t)3 * 3072 * 1024];  // l0=Wh0, l1/2=Whr
__device__ __align__(16) bf16 g_WhL[(size_t)3 * 3072 * 1024];
__device__ __align__(16) bf16 g_WxH[(size_t)2 * 3072 * 1024];  // Wxr
__device__ __align__(16) bf16 g_WxL[(size_t)2 * 3072 * 1024];
__device__ unsigned g_cnt;
__device__ volatile unsigned g_gen;

// ---------------- generic helpers ----------------
__device__ __forceinline__ u64 ffma2(u64 a, u64 b, u64 c) {
    u64 d;
    asm("fma.rn.f32x2 %0, %1, %2, %3;" : "=l"(d) : "l"(a), "l"(b), "l"(c));
    return d;
}
__device__ __forceinline__ float psum(u64 a) {
    float2 f = *reinterpret_cast<float2*>(&a);
    return f.x + f.y;
}
__device__ __forceinline__ float sigm(float x) { return 1.f / (1.f + __expf(-x)); }

__device__ __forceinline__ void gridbar() {
    __syncthreads();
    if (threadIdx.x == 0) {
        unsigned old = g_gen;
        __threadfence();
        if (atomicAdd(&g_cnt, 1u) == NCTA - 1) {
            g_cnt = 0;
            __threadfence();
            g_gen = old + 1;
        } else {
            while (g_gen == old) __nanosleep(32);
            __threadfence();
        }
    }
    __syncthreads();
}

// ---------------- mma / ldmatrix / cp.async primitives ----------------
__device__ __forceinline__ u32 smem_u32(const void* p) {
    u32 a;
    asm("{ .reg .u64 t; cvta.to.shared.u64 t, %1; cvt.u32.u64 %0, t; }" : "=r"(a) : "l"(p));
    return a;
}
__device__ __forceinline__ void mma16816(float* d, const u32* a, const u32* b) {
    asm volatile(
        "mma.sync.aligned.m16n8k16.row.col.f32.bf16.bf16.f32 "
        "{%0,%1,%2,%3}, {%4,%5,%6,%7}, {%8,%9}, {%0,%1,%2,%3};"
        : "+f"(d[0]), "+f"(d[1]), "+f"(d[2]), "+f"(d[3])
        : "r"(a[0]), "r"(a[1]), "r"(a[2]), "r"(a[3]), "r"(b[0]), "r"(b[1]));
}
__device__ __forceinline__ void ldm4(u32& r0, u32& r1, u32& r2, u32& r3, u32 addr) {
    asm volatile("ldmatrix.sync.aligned.m8n8.x4.shared.b16 {%0,%1,%2,%3}, [%4];"
                 : "=r"(r0), "=r"(r1), "=r"(r2), "=r"(r3) : "r"(addr));
}
__device__ __forceinline__ void cpa(u32 dst, const void* src) {
    asm volatile("cp.async.cg.shared.global [%0], [%1], 16;" :: "r"(dst), "l"(src) : "memory");
}
__device__ __forceinline__ void cp_commit() { asm volatile("cp.async.commit_group;" ::: "memory"); }
__device__ __forceinline__ void cp_waitN(int rem) {
    if (rem >= 3) asm volatile("cp.async.wait_group 3;" ::: "memory");
    else if (rem == 2) asm volatile("cp.async.wait_group 2;" ::: "memory");
    else if (rem == 1) asm volatile("cp.async.wait_group 1;" ::: "memory");
    else asm volatile("cp.async.wait_group 0;" ::: "memory");
}

struct Src { const bf16 *AH, *AL, *BH, *BL; };

// issue one K=64 chunk (A 128x64 hi/lo, B 32x64 hi/lo) into smem buffer (512 thr)
__device__ __forceinline__ void issue_chunk(u32 sbuf, const Src& s, int koff, int tid) {
#pragma unroll
    for (int it = 0; it < 2; it++) {
        int idx = tid + NTHR * it;
        int row = idx >> 3, c16 = idx & 7;
        u32 d = sbuf + row * 144 + c16 * 16;
        size_t so = (size_t)row * 1024 + koff + c16 * 8;
        cpa(d, s.AH + so);
        cpa(d + OFF_AL, s.AL + so);
    }
    if (tid < 256) {
        int row = tid >> 3, c16 = tid & 7;
        u32 d = sbuf + OFF_BH + row * 144 + c16 * 16;
        size_t so = (size_t)row * 1024 + koff + c16 * 8;
        cpa(d, s.BH + so);
        cpa(d + (OFF_BL - OFF_BH), s.BL + so);
    }
    cp_commit();
}

// compute one K=64 chunk: 16 warps = 8(M) x 2(N); warp tile m16 x n16
__device__ __forceinline__ void mma_chunk(u32 sbuf, float (&acc)[2][4], int mw, int nw,
                                          int lane) {
    const int arow = ((lane >> 3) & 1) * 8 + (lane & 7);
    const int akk = ((lane >> 4) & 1) * 8;
    const int brow = ((lane >> 4) & 1) * 8 + (lane & 7);
    const int bkk = ((lane >> 3) & 1) * 8;
#pragma unroll
    for (int ks = 0; ks < 4; ks++) {
        int kOff = ks * 16;
        u32 aH[4], aL[4];
        {
            int row = mw * 16 + arow;
            u32 ad = sbuf + row * 144 + (kOff + akk) * 2;
            ldm4(aH[0], aH[1], aH[2], aH[3], ad);
            ldm4(aL[0], aL[1], aL[2], aL[3], ad + OFF_AL);
        }
        u32 bH[2][2], bL[2][2];
        {
            int nrow = nw * 16 + brow;
            u32 bd = sbuf + OFF_BH + nrow * 144 + (kOff + bkk) * 2;
            u32 r0, r1, r2, r3;
            ldm4(r0, r1, r2, r3, bd);
            bH[0][0] = r0; bH[0][1] = r1; bH[1][0] = r2; bH[1][1] = r3;
            ldm4(r0, r1, r2, r3, bd + (OFF_BL - OFF_BH));
            bL[0][0] = r0; bL[0][1] = r1; bL[1][0] = r2; bL[1][1] = r3;
        }
#pragma unroll
        for (int nt = 0; nt < 2; nt++) {
            mma16816(acc[nt], aH, bH[nt]);
            mma16816(acc[nt], aH, bL[nt]);
            mma16816(acc[nt], aL, bH[nt]);
        }
    }
}

// run nsrc sources x 16 chunks (full K=1024), 5-stage ring, depth-4 prefetch
__device__ __forceinline__ void run_sources(const Src* s, int nsrc, u32 sm0,
                                            float (&acc)[2][4], int tid, int mw, int nw,
                                            int lane) {
    const int n = nsrc * 16;
#pragma unroll
    for (int j = 0; j < 4; j++)
        if (j < n) issue_chunk(sm0 + j * BUFSZ, s[j >> 4], (j & 15) * 64, tid);
    for (int i = 0; i < n; i++) {
        int rem = n - 1 - i;
        cp_waitN(rem < 3 ? rem : 3);
        __syncthreads();
        int nx = i + 4;
        if (nx < n)
            issue_chunk(sm0 + (nx % NSTAGE) * BUFSZ, s[nx >> 4], (nx & 15) * 64, tid);
        mma_chunk(sm0 + (i % NSTAGE) * BUFSZ, acc, mw, nw, lane);
    }
    __syncthreads();
}

__device__ __forceinline__ void zero_acc(float (&acc)[2][4]) {
#pragma unroll
    for (int j = 0; j < 2; j++)
#pragma unroll
        for (int e = 0; e < 4; e++) acc[j][e] = 0.f;
}

// ---------------- SIMT f32x2 GEMM (xpre / yout) ----------------
__device__ __forceinline__ void gemm_tile(const float* __restrict__ A, int lda,
                                          const float* __restrict__ W, int ldw,
                                          float* __restrict__ C, int cld,
                                          const float* __restrict__ bias, int nch,
                                          u64* __restrict__ Sm) {
    const int tid = threadIdx.x, tx = tid & 15, ty = tid >> 4;
    u64 acc[8][8];
#pragma unroll
    for (int i = 0; i < 8; i++)
#pragma unroll
        for (int j = 0; j < 8; j++) acc[i][j] = 0ull;
    u64 rA[8], rB[16];
#pragma unroll
    for (int it = 0; it < 8; it++) {
        int idx = tid + 128 * it, row = idx >> 4, k8 = idx & 15;
        rA[it] = *reinterpret_cast<const u64*>(A + (size_t)row * lda + (k8 << 1));
    }
#pragma unroll
    for (int it = 0; it < 16; it++) {
        int idx = tid + 128 * it, row = idx >> 4, k8 = idx & 15;
        rB[it] = *reinterpret_cast<const u64*>(W + (size_t)row * ldw + (k8 << 1));
    }
    for (int c = 0; c < nch; c++) {
        u64* Ab = Sm + (c & 1) * 3072;
        u64* Bb = Ab + 1024;
#pragma unroll
        for (int it = 0; it < 8; it++) {
            int idx = tid + 128 * it, row = idx >> 4, k8 = idx & 15;
            Ab[(row << 4) + (k8 ^ ((row >> 3) & 15))] = rA[it];
        }
#pragma unroll
        for (int it = 0; it < 16; it++) {
            int idx = tid + 128 * it, row = idx >> 4, k8 = idx & 15;
            Bb[(row << 4) + (k8 ^ ((row >> 3) & 15))] = rB[it];
        }
        __syncthreads();
        if (c + 1 < nch) {
            const float* A2 = A + (c + 1) * 32;
            const float* W2 = W + (c + 1) * 32;
#pragma unroll
            for (int it = 0; it < 8; it++) {
                int idx = tid + 128 * it, row = idx >> 4, k8 = idx & 15;
                rA[it] = *reinterpret_cast<const u64*>(A2 + (size_t)row * lda + (k8 << 1));
            }
#pragma unroll
            for (int it = 0; it < 16; it++) {
                int idx = tid + 128 * it, row = idx >> 4, k8 = idx & 15;
                rB[it] = *reinterpret_cast<const u64*>(W2 + (size_t)row * ldw + (k8 << 1));
            }
        }
#pragma unroll
        for (int k8 = 0; k8 < 16; k8++) {
            u64 a2[8], b2[8];
#pragma unroll
            for (int i = 0; i < 8; i++) a2[i] = Ab[((ty * 8 + i) << 4) + (k8 ^ ty)];
#pragma unroll
            for (int j = 0; j < 8; j++) b2[j] = Bb[((tx * 8 + j) << 4) + (k8 ^ tx)];
#pragma unroll
            for (int i = 0; i < 8; i++)
#pragma unroll
                for (int j = 0; j < 8; j++) acc[i][j] = ffma2(a2[i], b2[j], acc[i][j]);
        }
    }
#pragma unroll
    for (int i = 0; i < 8; i++)
#pragma unroll
        for (int j = 0; j < 8; j++) {
            float v = psum(acc[i][j]);
            if (bias) v += bias[tx * 8 + j];
            C[(size_t)(ty * 8 + i) * cld + tx * 8 + j] = v;
        }
    __syncthreads();
}

// ---------------- kernels ----------------
__global__ void k_pad() {}

__global__ void k_conv(const float* __restrict__ Wh0, const float* __restrict__ Whr,
                       const float* __restrict__ Wxr) {
    const size_t NWH = (size_t)3 * 3072 * 1024;
    const size_t NTOT = (size_t)5 * 3072 * 1024;
    for (size_t i = (size_t)blockIdx.x * blockDim.x + threadIdx.x; i < NTOT;
         i += (size_t)gridDim.x * blockDim.x) {
        float w;
        bf16 *H, *L;
        size_t o;
        if (i < NWH) {
            o = i;
            w = (i < (size_t)3072 * 1024) ? Wh0[i] : Whr[i - (size_t)3072 * 1024];
            H = g_WhH; L = g_WhL;
        } else {
            o = i - NWH;
            w = Wxr[o];
            H = g_WxH; L = g_WxL;
        }
        bf16 h = __float2bfloat16_rn(w);
        H[o] = h;
        L[o] = __float2bfloat16_rn(w - __bfloat162float(h));
    }
}

__global__ __launch_bounds__(128, 2) void k_xpre(const float* __restrict__ x,
                                                 const float* __restrict__ Wx0) {
    __shared__ __align__(16) u64 Sm[6144];
    int n0 = blockIdx.x * 128, s = blockIdx.y;
    gemm_tile(x + (size_t)s * 128, 512 * 128, Wx0 + (size_t)n0 * 128, 128,
              g_Xpre + (size_t)s * 64 * 3072 + n0, 3072, nullptr, 4, Sm);
}

// persistent wavefront GRU: mma.sync bf16-split, batch-split x2, 2 barriers/wave
__global__ __launch_bounds__(NTHR) void k_gru(const float* __restrict__ bh0,
                                              const float* __restrict__ bhr) {
    extern __shared__ __align__(16) char dsm[];
    const u32 sm0 = smem_u32(dsm);
    const int tid = threadIdx.x, wid = tid >> 5, lane = tid & 31;
    const int mw = wid >> 1, nw = wid & 1;  // 8 M-warps x 2 N-warps
    const int cta = blockIdx.x;
    const int gtid = cta * NTHR + tid;

    for (int i = gtid; i < 2 * 3 * 65536; i += NCTA * NTHR) {
        (&g_hbuf[0][0][0])[i] = 0.f;
        (&g_hbH[0][0][0])[i] = __float2bfloat16_rn(0.f);
        (&g_hbL[0][0][0])[i] = __float2bfloat16_rn(0.f);
    }
    gridbar();

    // roles: cta<96 zr (l=cta/32, tt=(cta%32)/2, nh=cta&1); cta in [96,144) g
    int role, l = 0, tt = 0, nh = 0;
    if (cta < 96) { role = 0; l = cta >> 5; tt = (cta & 31) >> 1; nh = cta & 1; }
    else if (cta < 144) { int gi = cta - 96; role = 1; l = gi >> 4; tt = (gi & 15) >> 1; nh = gi & 1; }
    else role = 2;
    const int boff = nh * 32;           // batch-column offset of this CTA
    const size_t bptr = (size_t)boff * 1024;
    const int rlo = lane >> 2, cb = (lane & 3) * 2;

    float acc[2][4];

    for (int w = 0; w < 514; ++w) {
        const int rd = w & 1, wb = rd ^ 1;
        const int t = w - l;
        const bool act = (role < 2) && t >= 0 && t < 512;

        // ======== P1: zr full GEMMs + g x-path ========
        if (act && role == 0) {
            zero_acc(acc);
            Src s[2];
            int ns = 0;
            if (l > 0) {
                s[ns].AH = g_WxH + ((size_t)(l - 1) * 3072 + tt * 128) * 1024;
                s[ns].AL = g_WxL + ((size_t)(l - 1) * 3072 + tt * 128) * 1024;
                s[ns].BH = g_hbH[rd][l - 1] + bptr;
                s[ns].BL = g_hbL[rd][l - 1] + bptr;
                ns++;
            }
            s[ns].AH = g_WhH + ((size_t)l * 3072 + tt * 128) * 1024;
            s[ns].AL = g_WhL + ((size_t)l * 3072 + tt * 128) * 1024;
            s[ns].BH = g_hbH[rd][l] + bptr;
            s[ns].BL = g_hbL[rd][l] + bptr;
            ns++;
            run_sources(s, ns, sm0, acc, tid, mw, nw, lane);
            // epilogue: z (n<1024) or rh (n>=1024)
            const float* bias = (l == 0) ? bh0 : bhr + (l - 1) * 3072;
#pragma unroll
            for (int half = 0; half < 2; half++) {
                int mrow = mw * 16 + half * 8 + rlo;
                int n = tt * 128 + mrow;
                float bv = bias[n];
                if (n < 1024) {
#pragma unroll
                    for (int nt = 0; nt < 2; nt++)
#pragma unroll
                        for (int e = 0; e < 2; e++) {
                            int b = boff + nw * 16 + nt * 8 + cb + e;
                            float v = acc[nt][half * 2 + e] + bv;
                            if (l == 0) v += g_Xpre[((size_t)t * 64 + b) * 3072 + n];
                            g_z[l][b * 1024 + n] = sigm(v);
                        }
                } else {
                    int nn = n - 1024;
#pragma unroll
                    for (int nt = 0; nt < 2; nt++)
#pragma unroll
                        for (int e = 0; e < 2; e++) {
                            int b = boff + nw * 16 + nt * 8 + cb + e;
                            float v = acc[nt][half * 2 + e] + bv;
                            if (l == 0) v += g_Xpre[((size_t)t * 64 + b) * 3072 + n];
                            float rv = sigm(v) * g_hbuf[rd][l][b * 1024 + nn];
                            bf16 hi = __float2bfloat16_rn(rv);
                            g_rhH[l][b * 1024 + nn] = hi;
                            g_rhL[l][b * 1024 + nn] =
                                __float2bfloat16_rn(rv - __bfloat162float(hi));
                        }
                }
            }
        } else if (act && role == 1) {
            zero_acc(acc);
            if (l > 0) {
                Src s;
                s.AH = g_WxH + ((size_t)(l - 1) * 3072 + 2048 + tt * 128) * 1024;
                s.AL = g_WxL + ((size_t)(l - 1) * 3072 + 2048 + tt * 128) * 1024;
                s.BH = g_hbH[rd][l - 1] + bptr;
                s.BL = g_hbL[rd][l - 1] + bptr;
                run_sources(&s, 1, sm0, acc, tid, mw, nw, lane);
            }
        }
        gridbar();

        // ======== P2: g rh-path + epilogue ========
        if (act && role == 1) {
            Src s;
            s.AH = g_WhH + ((size_t)l * 3072 + 2048 + tt * 128) * 1024;
            s.AL = g_WhL + ((size_t)l * 3072 + 2048 + tt * 128) * 1024;
            s.BH = g_rhH[l] + bptr;
            s.BL = g_rhL[l] + bptr;
            run_sources(&s, 1, sm0, acc, tid, mw, nw, lane);
            const float* bias = (l == 0) ? bh0 : bhr + (l - 1) * 3072;
#pragma unroll
            for (int half = 0; half < 2; half++) {
                int mrow = mw * 16 + half * 8 + rlo;
                int gc = tt * 128 + mrow;
                float bv = bias[2048 + gc];
#pragma unroll
                for (int nt = 0; nt < 2; nt++)
#pragma unroll
                    for (int e = 0; e < 2; e++) {
                        int b = boff + nw * 16 + nt * 8 + cb + e;
                        float v = acc[nt][half * 2 + e] + bv;
                        if (l == 0) v += g_Xpre[((size_t)t * 64 + b) * 3072 + 2048 + gc];
                        float gg = tanhf(v);
                        float z = g_z[l][b * 1024 + gc];
                        float hp = g_hbuf[rd][l][b * 1024 + gc];
                        float hn = z * hp + (1.f - z) * gg;
                        g_hbuf[wb][l][b * 1024 + gc] = hn;
                        bf16 hi = __float2bfloat16_rn(hn);
                        g_hbH[wb][l][b * 1024 + gc] = hi;
                        g_hbL[wb][l][b * 1024 + gc] =
                            __float2bfloat16_rn(hn - __bfloat162float(hi));
                        if (l == 2) g_H2[((size_t)t * 64 + b) * 1024 + gc] = hn;
                    }
            }
        }
        gridbar();
    }
}

__global__ __launch_bounds__(128, 2) void k_yout(const float* __restrict__ Wout,
                                                 const float* __restrict__ bout,
                                                 float* __restrict__ out) {
    __shared__ __align__(16) u64 Sm[6144];
    int s = blockIdx.x;
    gemm_tile(g_H2 + (size_t)s * 64 * 1024, 1024, Wout, 1024,
              out + (size_t)s * 128, 512 * 128, bout, 32, Sm);
}

__global__ void k_hout(float* __restrict__ out) {
    int i = blockIdx.x * 256 + threadIdx.x;
    if (i >= 3 * 64 * 1024) return;
    int l = i / (64 * 1024);
    int r = i % (64 * 1024);
    int b = r / 1024, n = r % 1024;
    out[(size_t)64 * 512 * 128 + ((size_t)b * 3 + l) * 1024 + n] = g_hbuf[l & 1][l][r];
}

extern "C" void kernel_launch(void* const* d_in, const int* in_sizes, int n_in,
                              void* d_out, int out_size) {
    const float* x = (const float*)d_in[0];
    const float* Wx0 = (const float*)d_in[1];
    const float* Wh0 = (const float*)d_in[2];
    const float* bh0 = (const float*)d_in[3];
    const float* Wxr = (const float*)d_in[4];
    const float* Whr = (const float*)d_in[5];
    const float* bhr = (const float*)d_in[6];
    const float* Wout = (const float*)d_in[7];
    const float* bout = (const float*)d_in[8];
    float* out = (float*)d_out;

    cudaFuncSetAttribute(k_gru, cudaFuncAttributeMaxDynamicSharedMemorySize, NSTAGE * BUFSZ);

    k_pad<<<1, 32>>>();
    k_conv<<<2048, 256>>>(Wh0, Whr, Wxr);
    k_xpre<<<dim3(24, 512), 128>>>(x, Wx0);
    k_gru<<<NCTA, NTHR, NSTAGE * BUFSZ>>>(bh0, bhr);  // my 4th launch -> ncu -s 5
    k_yout<<<512, 128>>>(Wout, bout, out);
    k_hout<<<(3 * 64 * 1024 + 255) / 256, 256>>>(out);
}